// round 4
// baseline (speedup 1.0000x reference)
#include <cuda_runtime.h>
#include <cuda_bf16.h>

// out = -0.1f * x over 67,108,864 fp32 elements (256 MiB in + 256 MiB out).
// Pure HBM stream at the bus ceiling. Measured sweep: ITEMS=4 is the MLP
// optimum. This round: exact-fit (no predication) + 512-thread blocks.

#define ITEMS 4
#define THREADS 512

// Exact-fit: grid covers n4 exactly, no bounds checks.
__global__ void __launch_bounds__(THREADS)
scale_kernel_exact(const float4* __restrict__ x,
                   float4* __restrict__ out) {
    int base = blockIdx.x * (THREADS * ITEMS) + threadIdx.x;

    float4 v[ITEMS];
    #pragma unroll
    for (int k = 0; k < ITEMS; k++) {
        v[k] = __ldcs(&x[base + k * THREADS]);
    }

    #pragma unroll
    for (int k = 0; k < ITEMS; k++) {
        float4 r;
        r.x = -0.1f * v[k].x;
        r.y = -0.1f * v[k].y;
        r.z = -0.1f * v[k].z;
        r.w = -0.1f * v[k].w;
        __stcs(&out[base + k * THREADS], r);
    }
}

// Guarded generic kernel for sizes that don't divide evenly.
__global__ void __launch_bounds__(THREADS)
scale_kernel_guarded(const float4* __restrict__ x,
                     float4* __restrict__ out,
                     int n4) {
    int base = blockIdx.x * (THREADS * ITEMS) + threadIdx.x;
    #pragma unroll
    for (int k = 0; k < ITEMS; k++) {
        int i = base + k * THREADS;
        if (i < n4) {
            float4 v = __ldcs(&x[i]);
            float4 r;
            r.x = -0.1f * v.x;
            r.y = -0.1f * v.y;
            r.z = -0.1f * v.z;
            r.w = -0.1f * v.w;
            __stcs(&out[i], r);
        }
    }
}

// Scalar tail for element counts not divisible by 4.
__global__ void scale_kernel_tail(const float* __restrict__ x,
                                  float* __restrict__ out,
                                  int start, int n) {
    int i = start + blockIdx.x * blockDim.x + threadIdx.x;
    if (i < n) {
        out[i] = -0.1f * x[i];
    }
}

extern "C" void kernel_launch(void* const* d_in, const int* in_sizes, int n_in,
                              void* d_out, int out_size) {
    const float* x = (const float*)d_in[0];
    float* out = (float*)d_out;
    int n = in_sizes[0];

    int n4 = n / 4;
    const int per_block = THREADS * ITEMS;
    if (n4 > 0) {
        if (n4 % per_block == 0) {
            scale_kernel_exact<<<n4 / per_block, THREADS>>>(
                (const float4*)x, (float4*)out);
        } else {
            int blocks = (n4 + per_block - 1) / per_block;
            scale_kernel_guarded<<<blocks, THREADS>>>(
                (const float4*)x, (float4*)out, n4);
        }
    }
    int tail_start = n4 * 4;
    int tail = n - tail_start;
    if (tail > 0) {
        scale_kernel_tail<<<1, 256>>>(x, out, tail_start, n);
    }
}